// round 11
// baseline (speedup 1.0000x reference)
#include <cuda_runtime.h>

#define NQ  8
#define DIM 256
#define SQ2 0.70710678118654752f

__device__ __align__(16) float2 g_psi[DIM];
__device__ volatile int g_flag;   // zero-init; reset by last worker
__device__ int g_done;            // zero-init; reset by last worker

__device__ __constant__ unsigned char PI_[28] =
    {0,0,0,0,0,0,0,1,1,1,1,1,1,2,2,2,2,2,3,3,3,3,4,4,4,5,5,6};
__device__ __constant__ unsigned char PJ_[28] =
    {1,2,3,4,5,6,7,2,3,4,5,6,7,3,4,5,6,7,4,5,6,7,5,6,7,6,7,7};

__device__ __forceinline__ float2 cmul(float2 a, float2 b) {
    return make_float2(a.x * b.x - a.y * b.y, a.x * b.y + a.y * b.x);
}
__device__ __forceinline__ float2 cmad(float2 acc, float2 a, float2 b) {
    return make_float2(acc.x + a.x * b.x - a.y * b.y,
                       acc.y + a.x * b.y + a.y * b.x);
}

// ---------------------------------------------------------------------------
// grid = 65: block 0 evolves; blocks 1..64 spin then write output directly.
// ---------------------------------------------------------------------------
__global__ void __launch_bounds__(256, 1)
fused_kernel(const float* __restrict__ x,
             const float* __restrict__ w,
             const float* __restrict__ cplg,
             float4* __restrict__ out) {
    const int tid = threadIdx.x;

    // ================= worker blocks =================
    if (blockIdx.x != 0) {
        while (g_flag == 0) {}
        __threadfence();
        const int r = ((blockIdx.x - 1) << 2) | (tid >> 6);
        const int q = tid & 63;
        const float2 a   = __ldcg(&g_psi[r]);
        const float4 B01 = __ldcg((const float4*)&g_psi[q << 2]);
        const float4 B23 = __ldcg((const float4*)&g_psi[(q << 2) + 2]);
        float4 o;
        o.x = a.x * B01.x + a.y * B01.y;
        o.y = a.x * B01.z + a.y * B01.w;
        o.z = a.x * B23.x + a.y * B23.y;
        o.w = a.x * B23.z + a.y * B23.w;
        out[(r << 6) + q] = o;

        __syncthreads();
        if (tid == 0) {
            const int old = atomicAdd(&g_done, 1);
            if (old == 63) {
                g_done = 0;
                __threadfence();
                g_flag = 0;
            }
        }
        return;
    }

    // ================= block 0: evolution =================
    __shared__ float2 buf[2][DIM];
    __shared__ float2 pairM[28][16];
    __shared__ float2 u1s[8][4];     // H * (Rz Ry Rx), per qubit
    __shared__ float2 u4a[256];      // (u1 x u1 x u1 x u1) qubits 0-3
    __shared__ float2 u4b[256];      // qubits 4-7
    __shared__ float2 sD[DIM];       // ising diagonal phases
    __shared__ float  sw[210];
    __shared__ float  scpl[64];
    __shared__ float  red[8];
    __shared__ int    actL[28];
    __shared__ int    actN_sh;
    __shared__ unsigned amask_sh;

    const int lane = tid & 31;
    const int wid  = tid >> 5;

    if (tid < 210) sw[tid]   = w[tid];
    if (tid < 64)  scpl[tid] = cplg[tid];
    const float xv = x[tid];
    float ssum = xv * xv;
#pragma unroll
    for (int o = 16; o; o >>= 1) ssum += __shfl_xor_sync(0xffffffffu, ssum, o);
    if (lane == 0) red[wid] = ssum;
    __syncthreads();                               // sync0

    // ---------------- phase 1 ----------------
    const float inv = rsqrtf(red[0] + red[1] + red[2] + red[3] +
                             red[4] + red[5] + red[6] + red[7]);
    buf[0][tid] = make_float2(xv * inv, 0.f);

    {   // per-thread ising diagonal phase
        float th = 0.f;
#pragma unroll
        for (int p = 0; p < 28; p++) {
            const int i = PI_[p], j = PJ_[p];
            const float phi = scpl[i * 8 + j];
            const int b = ((tid >> (7 - i)) ^ (tid >> (7 - j))) & 1;
            th += b ? -0.5f * phi : 0.5f * phi;
        }
        float s, c;
        __sincosf(th, &s, &c);
        sD[tid] = make_float2(c, -s);
    }

    if (wid == 0) {
        float mn = fminf(scpl[lane], scpl[lane + 32]);
        float mx = fmaxf(scpl[lane], scpl[lane + 32]);
#pragma unroll
        for (int o = 16; o; o >>= 1) {
            mn = fminf(mn, __shfl_xor_sync(0xffffffffu, mn, o));
            mx = fmaxf(mx, __shfl_xor_sync(0xffffffffu, mx, o));
        }
        const float range = mx - mn;
        bool bit = false;
        if (lane < 28)
            bit = (scpl[PI_[lane] * 8 + PJ_[lane]] - mn) / range > 0.5f;
        const unsigned am = __ballot_sync(0xffffffffu, bit);
        if (lane == 0) amask_sh = am;
    } else if (tid >= 128 && tid < 136) {
        // u' = H * Rz*Ry*Rx for qubit q
        const int q = tid - 128;
        float sx, cx, sy, cy, sz, cz;
        __sincosf(0.5f * sw[q],      &sx, &cx);
        __sincosf(0.5f * sw[q + 8],  &sy, &cy);
        __sincosf(0.5f * sw[q + 16], &sz, &cz);
        const float2 A00 = make_float2(cy * cx,  sy * sx);
        const float2 A01 = make_float2(-sy * cx, -cy * sx);
        const float2 A10 = make_float2( sy * cx, -cy * sx);
        const float2 A11 = make_float2(cy * cx, -sy * sx);
        const float2 ez  = make_float2(cz, -sz);
        const float2 ezc = make_float2(cz,  sz);
        const float2 u00 = cmul(ez,  A00);
        const float2 u01 = cmul(ez,  A01);
        const float2 u10 = cmul(ezc, A10);
        const float2 u11 = cmul(ezc, A11);
        u1s[q][0] = make_float2(SQ2 * (u00.x + u10.x), SQ2 * (u00.y + u10.y));
        u1s[q][1] = make_float2(SQ2 * (u01.x + u11.x), SQ2 * (u01.y + u11.y));
        u1s[q][2] = make_float2(SQ2 * (u00.x - u10.x), SQ2 * (u00.y - u10.y));
        u1s[q][3] = make_float2(SQ2 * (u01.x - u11.x), SQ2 * (u01.y - u11.y));
    }
    __syncthreads();                               // sync1: amask, u1s, sD
    const unsigned amask = amask_sh;

    // ---------------- phase 2 ----------------
    // every thread builds one entry of u4a and u4b (row=t>>4, col=t&15)
    {
        const int row = tid >> 4, col = tid & 15;
        const int r0 = (row >> 3) & 1, r1 = (row >> 2) & 1, r2 = (row >> 1) & 1, r3 = row & 1;
        const int c0 = (col >> 3) & 1, c1 = (col >> 2) & 1, c2 = (col >> 1) & 1, c3 = col & 1;
        float2 ea = cmul(u1s[0][r0 * 2 + c0], u1s[1][r1 * 2 + c1]);
        ea = cmul(ea, u1s[2][r2 * 2 + c2]);
        ea = cmul(ea, u1s[3][r3 * 2 + c3]);
        u4a[tid] = ea;
        float2 eb = cmul(u1s[4][r0 * 2 + c0], u1s[5][r1 * 2 + c1]);
        eb = cmul(eb, u1s[6][r2 * 2 + c2]);
        eb = cmul(eb, u1s[7][r3 * 2 + c3]);
        u4b[tid] = eb;
    }

    if (tid < 112) {
        const int p   = tid >> 2;
        const int col = tid & 3;
        const int widx = 3 * NQ + 6 * __popc(amask & ((1u << p) - 1u));

        float2 v0 = make_float2(col == 0 ? 1.f : 0.f, 0.f);
        float2 v1 = make_float2(col == 1 ? 1.f : 0.f, 0.f);
        float2 v2 = make_float2(col == 2 ? 1.f : 0.f, 0.f);
        float2 v3 = make_float2(col == 3 ? 1.f : 0.f, 0.f);

#define PHASE_I(er, ei) { const float2 e = make_float2(er, ei), ec = make_float2(er, -(ei)); \
        v0 = cmul(v0, e); v1 = cmul(v1, e); v2 = cmul(v2, ec); v3 = cmul(v3, ec); }
#define PHASE_J(er, ei) { const float2 e = make_float2(er, ei), ec = make_float2(er, -(ei)); \
        v0 = cmul(v0, e); v1 = cmul(v1, ec); v2 = cmul(v2, e); v3 = cmul(v3, ec); }
#define RY_J(c, s) { float2 t; \
        t  = make_float2((c)*v0.x - (s)*v1.x, (c)*v0.y - (s)*v1.y); \
        v1 = make_float2((s)*v0.x + (c)*v1.x, (s)*v0.y + (c)*v1.y); v0 = t; \
        t  = make_float2((c)*v2.x - (s)*v3.x, (c)*v2.y - (s)*v3.y); \
        v3 = make_float2((s)*v2.x + (c)*v3.x, (s)*v2.y + (c)*v3.y); v2 = t; }
#define SWAP13 { const float2 t = v1; v1 = v3; v3 = t; }
#define SWAP23 { const float2 t = v2; v2 = v3; v3 = t; }

        float s0, c0, s1, c1, s2, c2, s3, c3, s4, c4, s5, c5;
        __sincosf(0.5f * sw[widx + 0], &s0, &c0);
        __sincosf(0.5f * sw[widx + 1], &s1, &c1);
        __sincosf(0.5f * sw[widx + 2], &s2, &c2);
        __sincosf(0.5f * sw[widx + 3], &s3, &c3);
        __sincosf(0.5f * sw[widx + 4], &s4, &c4);
        __sincosf(0.5f * sw[widx + 5], &s5, &c5);

        PHASE_J(SQ2,  SQ2);
        SWAP13;
        PHASE_I(c0, -s0);
        RY_J(c1, s1);
        SWAP23;
        RY_J(c2, s2);
        SWAP13;
        PHASE_I(SQ2, -SQ2);
        PHASE_J(SQ2,  SQ2);
        SWAP13;
        PHASE_I(c3, -s3);
        RY_J(c4, s4);
        SWAP23;
        RY_J(c5, s5);

        pairM[p][0 * 4 + col] = v0;
        pairM[p][1 * 4 + col] = v1;
        pairM[p][2 * 4 + col] = v2;
        pairM[p][3 * 4 + col] = v3;
#undef PHASE_I
#undef PHASE_J
#undef RY_J
#undef SWAP13
#undef SWAP23
    } else if (tid == 192) {
        int n = 0;
#pragma unroll
        for (int p = 0; p < 28; p++) {
            if ((amask >> p) & 1u) {
                actL[n++] = p | ((1 << (7 - PI_[p])) << 8)
                              | ((1 << (7 - PJ_[p])) << 16);
            }
        }
        actN_sh = n;
    }
    __syncthreads();                               // sync2: chain start
    const int actN = actN_sh;

    int cp = 0;

    // ---- 1q step A: 16x16 on bits 7..4 ----
    {
        const int base = tid & 15;
        const int row  = tid >> 4;
        const float2* M = &u4a[row << 4];
        float2 r0 = cmul(M[0], buf[cp][base]);
        float2 r1 = cmul(M[1], buf[cp][base | (1 << 4)]);
#pragma unroll
        for (int c = 2; c < 16; c += 2) {
            r0 = cmad(r0, M[c],     buf[cp][base | (c << 4)]);
            r1 = cmad(r1, M[c + 1], buf[cp][base | ((c + 1) << 4)]);
        }
        buf[cp ^ 1][tid] = make_float2(r0.x + r1.x, r0.y + r1.y);
        __syncthreads();
        cp ^= 1;
    }
    // ---- 1q step B: 16x16 on bits 3..0, ising diagonal folded in ----
    {
        const int base = tid & 0xF0;
        const int row  = tid & 15;
        const float2* M = &u4b[row << 4];
        float2 r0 = cmul(M[0], buf[cp][base]);
        float2 r1 = cmul(M[1], buf[cp][base | 1]);
#pragma unroll
        for (int c = 2; c < 16; c += 2) {
            r0 = cmad(r0, M[c],     buf[cp][base | c]);
            r1 = cmad(r1, M[c + 1], buf[cp][base | (c + 1)]);
        }
        buf[cp ^ 1][tid] = cmul(sD[tid], make_float2(r0.x + r1.x, r0.y + r1.y));
        __syncthreads();
        cp ^= 1;
    }

    // ---- H(x)4 step A: bits 7..4 ----
    {
        const int base = tid & 15;
        const int rb   = tid >> 4;
        float rx0 = 0.f, ry0 = 0.f, rx1 = 0.f, ry1 = 0.f;
#pragma unroll
        for (int v = 0; v < 16; v += 2) {
            const float2 a0 = buf[cp][base | (v << 4)];
            const float2 a1 = buf[cp][base | ((v + 1) << 4)];
            if (__popc(rb & v) & 1)       { rx0 -= a0.x; ry0 -= a0.y; }
            else                           { rx0 += a0.x; ry0 += a0.y; }
            if (__popc(rb & (v + 1)) & 1) { rx1 -= a1.x; ry1 -= a1.y; }
            else                           { rx1 += a1.x; ry1 += a1.y; }
        }
        buf[cp ^ 1][tid] = make_float2(0.25f * (rx0 + rx1), 0.25f * (ry0 + ry1));
        __syncthreads();
        cp ^= 1;
    }
    // ---- H(x)4 step B: bits 3..0 ----
    {
        const int base = tid & 0xF0;
        const int rb   = tid & 15;
        float rx0 = 0.f, ry0 = 0.f, rx1 = 0.f, ry1 = 0.f;
#pragma unroll
        for (int v = 0; v < 16; v += 2) {
            const float2 a0 = buf[cp][base | v];
            const float2 a1 = buf[cp][base | (v + 1)];
            if (__popc(rb & v) & 1)       { rx0 -= a0.x; ry0 -= a0.y; }
            else                           { rx0 += a0.x; ry0 += a0.y; }
            if (__popc(rb & (v + 1)) & 1) { rx1 -= a1.x; ry1 -= a1.y; }
            else                           { rx1 += a1.x; ry1 += a1.y; }
        }
        buf[cp ^ 1][tid] = make_float2(0.25f * (rx0 + rx1), 0.25f * (ry0 + ry1));
        __syncthreads();
        cp ^= 1;
    }

    // ---- dense conv+pool 4x4 applies ----
#pragma unroll 1
    for (int a = 0; a < actN; a++) {
        const int packed = actL[a];
        const int p  = packed & 255;
        const int mi = (packed >> 8) & 255;
        const int mj = (packed >> 16) & 255;
        const int row  = ((tid & mi) ? 2 : 0) | ((tid & mj) ? 1 : 0);
        const int base = tid & ~(mi | mj);
        const float2* M = &pairM[p][row * 4];
        float2 r = cmul(M[0], buf[cp][base]);
        r = cmad(r, M[1], buf[cp][base | mj]);
        r = cmad(r, M[2], buf[cp][base | mi]);
        r = cmad(r, M[3], buf[cp][base | mi | mj]);
        buf[cp ^ 1][tid] = r;
        __syncthreads();
        cp ^= 1;
    }

    // publish state, release workers
    g_psi[tid] = buf[cp][tid];
    __threadfence();
    __syncthreads();
    if (tid == 0 && gridDim.x > 1) g_flag = 1;
}

// fallback for unexpected out_size (planar [Re|Im])
__global__ void __launch_bounds__(256)
outer_planar_kernel(float* __restrict__ out) {
    const int r = blockIdx.x;
    const int c = threadIdx.x;
    const float2 a = g_psi[r];
    const float2 b = g_psi[c];
    out[r * DIM + c]             = a.x * b.x + a.y * b.y;
    out[DIM * DIM + r * DIM + c] = a.y * b.x - a.x * b.y;
}

extern "C" void kernel_launch(void* const* d_in, const int* in_sizes, int n_in,
                              void* d_out, int out_size) {
    const float* x   = nullptr;
    const float* w   = nullptr;
    const float* cpl = nullptr;
    for (int i = 0; i < n_in; i++) {
        if      (in_sizes[i] == 256) x   = (const float*)d_in[i];
        else if (in_sizes[i] == 210) w   = (const float*)d_in[i];
        else if (in_sizes[i] == 64)  cpl = (const float*)d_in[i];
    }

    if (out_size == DIM * DIM) {
        fused_kernel<<<65, 256>>>(x, w, cpl, (float4*)d_out);
    } else {
        fused_kernel<<<1, 256>>>(x, w, cpl, (float4*)d_out);
        outer_planar_kernel<<<DIM, DIM>>>((float*)d_out);
    }
}

// round 12
// speedup vs baseline: 1.1591x; 1.1591x over previous
#include <cuda_runtime.h>

#define NQ  8
#define DIM 256
#define SQ2 0.70710678118654752f

__device__ __align__(16) float2 g_psi[DIM];

__device__ __constant__ unsigned char PI_[28] =
    {0,0,0,0,0,0,0,1,1,1,1,1,1,2,2,2,2,2,3,3,3,3,4,4,4,5,5,6};
__device__ __constant__ unsigned char PJ_[28] =
    {1,2,3,4,5,6,7,2,3,4,5,6,7,3,4,5,6,7,4,5,6,7,5,6,7,6,7,7};

__device__ __forceinline__ float2 cmul(float2 a, float2 b) {
    return make_float2(a.x * b.x - a.y * b.y, a.x * b.y + a.y * b.x);
}
__device__ __forceinline__ float2 cmad(float2 acc, float2 a, float2 b) {
    return make_float2(acc.x + a.x * b.x - a.y * b.y,
                       acc.y + a.x * b.y + a.y * b.x);
}

// ---------------------------------------------------------------------------
// Every block runs the IDENTICAL evolution (deterministic, bit-identical
// results), then writes its own 4-row slice of the output. No inter-block
// communication at all.
// ---------------------------------------------------------------------------
__global__ void __launch_bounds__(256, 1)
fused_kernel(const float* __restrict__ x,
             const float* __restrict__ w,
             const float* __restrict__ cplg,
             float4* __restrict__ out,
             int mode) {           // 0: write slice; 1: publish g_psi only
    const int tid = threadIdx.x;

    __shared__ float2 buf[2][DIM];
    __shared__ float2 pairM[28][16];
    __shared__ float2 u2s[4][16];
    __shared__ float2 u1s[8][4];     // H * (Rz Ry Rx), per qubit
    __shared__ float2 sD[DIM];       // ising diagonal phases
    __shared__ float  sw[210];
    __shared__ float  scpl[64];
    __shared__ float  red[8];
    __shared__ int    actL[28];
    __shared__ int    actN_sh;
    __shared__ unsigned amask_sh;

    const int lane = tid & 31;
    const int wid  = tid >> 5;

    if (tid < 210) sw[tid]   = w[tid];
    if (tid < 64)  scpl[tid] = cplg[tid];
    const float xv = x[tid];
    float ssum = xv * xv;
#pragma unroll
    for (int o = 16; o; o >>= 1) ssum += __shfl_xor_sync(0xffffffffu, ssum, o);
    if (lane == 0) red[wid] = ssum;
    __syncthreads();                               // sync0

    // ---------------- phase 1 ----------------
    const float inv = rsqrtf(red[0] + red[1] + red[2] + red[3] +
                             red[4] + red[5] + red[6] + red[7]);
    buf[0][tid] = make_float2(xv * inv, 0.f);

    {   // per-thread ising diagonal phase
        float th = 0.f;
#pragma unroll
        for (int p = 0; p < 28; p++) {
            const int i = PI_[p], j = PJ_[p];
            const float phi = scpl[i * 8 + j];
            const int b = ((tid >> (7 - i)) ^ (tid >> (7 - j))) & 1;
            th += b ? -0.5f * phi : 0.5f * phi;
        }
        float s, c;
        __sincosf(th, &s, &c);
        sD[tid] = make_float2(c, -s);
    }

    if (wid == 0) {
        float mn = fminf(scpl[lane], scpl[lane + 32]);
        float mx = fmaxf(scpl[lane], scpl[lane + 32]);
#pragma unroll
        for (int o = 16; o; o >>= 1) {
            mn = fminf(mn, __shfl_xor_sync(0xffffffffu, mn, o));
            mx = fmaxf(mx, __shfl_xor_sync(0xffffffffu, mx, o));
        }
        const float range = mx - mn;
        bool bit = false;
        if (lane < 28)
            bit = (scpl[PI_[lane] * 8 + PJ_[lane]] - mn) / range > 0.5f;
        const unsigned am = __ballot_sync(0xffffffffu, bit);
        if (lane == 0) amask_sh = am;
    } else if (tid >= 128 && tid < 136) {
        // u' = H * Rz*Ry*Rx for qubit q
        const int q = tid - 128;
        float sx, cx, sy, cy, sz, cz;
        __sincosf(0.5f * sw[q],      &sx, &cx);
        __sincosf(0.5f * sw[q + 8],  &sy, &cy);
        __sincosf(0.5f * sw[q + 16], &sz, &cz);
        const float2 A00 = make_float2(cy * cx,  sy * sx);
        const float2 A01 = make_float2(-sy * cx, -cy * sx);
        const float2 A10 = make_float2( sy * cx, -cy * sx);
        const float2 A11 = make_float2(cy * cx, -sy * sx);
        const float2 ez  = make_float2(cz, -sz);
        const float2 ezc = make_float2(cz,  sz);
        const float2 u00 = cmul(ez,  A00);
        const float2 u01 = cmul(ez,  A01);
        const float2 u10 = cmul(ezc, A10);
        const float2 u11 = cmul(ezc, A11);
        u1s[q][0] = make_float2(SQ2 * (u00.x + u10.x), SQ2 * (u00.y + u10.y));
        u1s[q][1] = make_float2(SQ2 * (u01.x + u11.x), SQ2 * (u01.y + u11.y));
        u1s[q][2] = make_float2(SQ2 * (u00.x - u10.x), SQ2 * (u00.y - u10.y));
        u1s[q][3] = make_float2(SQ2 * (u01.x - u11.x), SQ2 * (u01.y - u11.y));
    }
    __syncthreads();                               // sync1: amask, u1s, sD
    const unsigned amask = amask_sh;

    // ---------------- phase 2 ----------------
    if (tid < 112) {
        const int p   = tid >> 2;
        const int col = tid & 3;
        const int widx = 3 * NQ + 6 * __popc(amask & ((1u << p) - 1u));

        float2 v0 = make_float2(col == 0 ? 1.f : 0.f, 0.f);
        float2 v1 = make_float2(col == 1 ? 1.f : 0.f, 0.f);
        float2 v2 = make_float2(col == 2 ? 1.f : 0.f, 0.f);
        float2 v3 = make_float2(col == 3 ? 1.f : 0.f, 0.f);

#define PHASE_I(er, ei) { const float2 e = make_float2(er, ei), ec = make_float2(er, -(ei)); \
        v0 = cmul(v0, e); v1 = cmul(v1, e); v2 = cmul(v2, ec); v3 = cmul(v3, ec); }
#define PHASE_J(er, ei) { const float2 e = make_float2(er, ei), ec = make_float2(er, -(ei)); \
        v0 = cmul(v0, e); v1 = cmul(v1, ec); v2 = cmul(v2, e); v3 = cmul(v3, ec); }
#define RY_J(c, s) { float2 t; \
        t  = make_float2((c)*v0.x - (s)*v1.x, (c)*v0.y - (s)*v1.y); \
        v1 = make_float2((s)*v0.x + (c)*v1.x, (s)*v0.y + (c)*v1.y); v0 = t; \
        t  = make_float2((c)*v2.x - (s)*v3.x, (c)*v2.y - (s)*v3.y); \
        v3 = make_float2((s)*v2.x + (c)*v3.x, (s)*v2.y + (c)*v3.y); v2 = t; }
#define SWAP13 { const float2 t = v1; v1 = v3; v3 = t; }
#define SWAP23 { const float2 t = v2; v2 = v3; v3 = t; }

        float s0, c0, s1, c1, s2, c2, s3, c3, s4, c4, s5, c5;
        __sincosf(0.5f * sw[widx + 0], &s0, &c0);
        __sincosf(0.5f * sw[widx + 1], &s1, &c1);
        __sincosf(0.5f * sw[widx + 2], &s2, &c2);
        __sincosf(0.5f * sw[widx + 3], &s3, &c3);
        __sincosf(0.5f * sw[widx + 4], &s4, &c4);
        __sincosf(0.5f * sw[widx + 5], &s5, &c5);

        PHASE_J(SQ2,  SQ2);
        SWAP13;
        PHASE_I(c0, -s0);
        RY_J(c1, s1);
        SWAP23;
        RY_J(c2, s2);
        SWAP13;
        PHASE_I(SQ2, -SQ2);
        PHASE_J(SQ2,  SQ2);
        SWAP13;
        PHASE_I(c3, -s3);
        RY_J(c4, s4);
        SWAP23;
        RY_J(c5, s5);

        pairM[p][0 * 4 + col] = v0;
        pairM[p][1 * 4 + col] = v1;
        pairM[p][2 * 4 + col] = v2;
        pairM[p][3 * 4 + col] = v3;
#undef PHASE_I
#undef PHASE_J
#undef RY_J
#undef SWAP13
#undef SWAP23
    } else if (tid < 176) {
        const int t   = tid - 112;
        const int g   = t >> 4;
        const int row = (t >> 2) & 3;
        const int col = t & 3;
        const float2 ea = u1s[2 * g][(row >> 1) * 2 + (col >> 1)];
        const float2 eb = u1s[2 * g + 1][(row & 1) * 2 + (col & 1)];
        u2s[g][row * 4 + col] = cmul(ea, eb);
    } else if (tid == 192) {
        int n = 0;
#pragma unroll
        for (int p = 0; p < 28; p++) {
            if ((amask >> p) & 1u) {
                actL[n++] = p | ((1 << (7 - PI_[p])) << 8)
                              | ((1 << (7 - PJ_[p])) << 16);
            }
        }
        actN_sh = n;
    }
    __syncthreads();                               // sync2: chain start
    const int actN = actN_sh;

    int cp = 0;

    // ---- 3 paired single-qubit 4x4 steps (H folded) ----
#pragma unroll 1
    for (int g = 0; g < 3; g++) {
        const int ba = 7 - 2 * g, bb = 6 - 2 * g;
        const int ma = 1 << ba, mb = 1 << bb;
        const int row  = (((tid >> ba) & 1) << 1) | ((tid >> bb) & 1);
        const int base = tid & ~(ma | mb);
        const float2* M = &u2s[g][row * 4];
        float2 r = cmul(M[0], buf[cp][base]);
        r = cmad(r, M[1], buf[cp][base | mb]);
        r = cmad(r, M[2], buf[cp][base | ma]);
        r = cmad(r, M[3], buf[cp][base | ma | mb]);
        buf[cp ^ 1][tid] = r;
        __syncthreads();
        cp ^= 1;
    }
    // ---- 4th paired step, ising diagonal folded into the write ----
    {
        const int ma = 2, mb = 1;
        const int row  = (tid & 3);
        const int base = tid & ~3;
        const float2* M = &u2s[3][row * 4];
        float2 r = cmul(M[0], buf[cp][base]);
        r = cmad(r, M[1], buf[cp][base | mb]);
        r = cmad(r, M[2], buf[cp][base | ma]);
        r = cmad(r, M[3], buf[cp][base | ma | mb]);
        buf[cp ^ 1][tid] = cmul(sD[tid], r);
        __syncthreads();
        cp ^= 1;
    }

    // ---- 4 H(x)H steps ----
#pragma unroll 1
    for (int g = 0; g < 4; g++) {
        const int ba = 7 - 2 * g, bb = 6 - 2 * g;
        const int ma = 1 << ba, mb = 1 << bb;
        const int base = tid & ~(ma | mb);
        const float sa = (tid & ma) ? -1.f : 1.f;
        const float sb = (tid & mb) ? -1.f : 1.f;
        const float2 a00 = buf[cp][base];
        const float2 a01 = buf[cp][base | mb];
        const float2 a10 = buf[cp][base | ma];
        const float2 a11 = buf[cp][base | ma | mb];
        float2 r;
        r.x = 0.5f * ((a00.x + sb * a01.x) + sa * (a10.x + sb * a11.x));
        r.y = 0.5f * ((a00.y + sb * a01.y) + sa * (a10.y + sb * a11.y));
        buf[cp ^ 1][tid] = r;
        __syncthreads();
        cp ^= 1;
    }

    // ---- dense conv+pool 4x4 applies ----
#pragma unroll 1
    for (int a = 0; a < actN; a++) {
        const int packed = actL[a];
        const int p  = packed & 255;
        const int mi = (packed >> 8) & 255;
        const int mj = (packed >> 16) & 255;
        const int row  = ((tid & mi) ? 2 : 0) | ((tid & mj) ? 1 : 0);
        const int base = tid & ~(mi | mj);
        const float2* M = &pairM[p][row * 4];
        float2 r = cmul(M[0], buf[cp][base]);
        r = cmad(r, M[1], buf[cp][base | mj]);
        r = cmad(r, M[2], buf[cp][base | mi]);
        r = cmad(r, M[3], buf[cp][base | mi | mj]);
        buf[cp ^ 1][tid] = r;
        __syncthreads();
        cp ^= 1;
    }

    if (mode == 1) {                 // fallback path: publish state only
        g_psi[tid] = buf[cp][tid];
        return;
    }

    // ---- write this block's 4-row output slice (real part) ----
    const float2* ps = buf[cp];
    const int r = (blockIdx.x << 2) | (tid >> 6);
    const int q = tid & 63;
    const float2 a  = ps[r];
    const float2 b0 = ps[(q << 2)];
    const float2 b1 = ps[(q << 2) + 1];
    const float2 b2 = ps[(q << 2) + 2];
    const float2 b3 = ps[(q << 2) + 3];
    float4 o;
    o.x = a.x * b0.x + a.y * b0.y;
    o.y = a.x * b1.x + a.y * b1.y;
    o.z = a.x * b2.x + a.y * b2.y;
    o.w = a.x * b3.x + a.y * b3.y;
    out[(r << 6) + q] = o;
}

// fallback for unexpected out_size (planar [Re|Im])
__global__ void __launch_bounds__(256)
outer_planar_kernel(float* __restrict__ out) {
    const int r = blockIdx.x;
    const int c = threadIdx.x;
    const float2 a = g_psi[r];
    const float2 b = g_psi[c];
    out[r * DIM + c]             = a.x * b.x + a.y * b.y;
    out[DIM * DIM + r * DIM + c] = a.y * b.x - a.x * b.y;
}

extern "C" void kernel_launch(void* const* d_in, const int* in_sizes, int n_in,
                              void* d_out, int out_size) {
    const float* x   = nullptr;
    const float* w   = nullptr;
    const float* cpl = nullptr;
    for (int i = 0; i < n_in; i++) {
        if      (in_sizes[i] == 256) x   = (const float*)d_in[i];
        else if (in_sizes[i] == 210) w   = (const float*)d_in[i];
        else if (in_sizes[i] == 64)  cpl = (const float*)d_in[i];
    }

    if (out_size == DIM * DIM) {
        fused_kernel<<<64, 256>>>(x, w, cpl, (float4*)d_out, 0);
    } else {
        fused_kernel<<<1, 256>>>(x, w, cpl, (float4*)d_out, 1);
        outer_planar_kernel<<<DIM, DIM>>>((float*)d_out);
    }
}

// round 13
// speedup vs baseline: 1.5000x; 1.2941x over previous
#include <cuda_runtime.h>

#define NQ  8
#define DIM 256
#define SQ2 0.70710678118654752f

__device__ __align__(16) float2 g_psi[DIM];

__device__ __constant__ unsigned char PI_[28] =
    {0,0,0,0,0,0,0,1,1,1,1,1,1,2,2,2,2,2,3,3,3,3,4,4,4,5,5,6};
__device__ __constant__ unsigned char PJ_[28] =
    {1,2,3,4,5,6,7,2,3,4,5,6,7,3,4,5,6,7,4,5,6,7,5,6,7,6,7,7};

__device__ __forceinline__ float2 cmul(float2 a, float2 b) {
    return make_float2(a.x * b.x - a.y * b.y, a.x * b.y + a.y * b.x);
}
__device__ __forceinline__ float2 cmad(float2 acc, float2 a, float2 b) {
    return make_float2(acc.x + a.x * b.x - a.y * b.y,
                       acc.y + a.x * b.y + a.y * b.x);
}

// ---------------------------------------------------------------------------
// Every block runs the IDENTICAL evolution, then writes its own 4-row output
// slice. Steps whose gather mask stays inside one warp's 32-amp segment use
// __syncwarp instead of __syncthreads.
// ---------------------------------------------------------------------------
__global__ void __launch_bounds__(256, 1)
fused_kernel(const float* __restrict__ x,
             const float* __restrict__ w,
             const float* __restrict__ cplg,
             float4* __restrict__ out,
             int mode) {           // 0: write slice; 1: publish g_psi only
    const int tid = threadIdx.x;

    __shared__ float2 buf[2][DIM];
    __shared__ float2 pairM[28][16];
    __shared__ float2 u2s[4][16];
    __shared__ float2 u1s[8][4];
    __shared__ float2 sD[DIM];
    __shared__ float  sw[210];
    __shared__ float  scpl[64];
    __shared__ float  red[8];
    __shared__ int    actL[28];
    __shared__ int    actN_sh;
    __shared__ unsigned amask_sh;

    const int lane = tid & 31;
    const int wid  = tid >> 5;

    if (tid < 210) sw[tid]   = w[tid];
    if (tid < 64)  scpl[tid] = cplg[tid];
    const float xv = x[tid];
    float ssum = xv * xv;
#pragma unroll
    for (int o = 16; o; o >>= 1) ssum += __shfl_xor_sync(0xffffffffu, ssum, o);
    if (lane == 0) red[wid] = ssum;
    __syncthreads();                               // sync0

    // ---------------- phase 1 ----------------
    const float inv = rsqrtf(red[0] + red[1] + red[2] + red[3] +
                             red[4] + red[5] + red[6] + red[7]);
    buf[0][tid] = make_float2(xv * inv, 0.f);

    {   // per-thread ising diagonal phase
        float th = 0.f;
#pragma unroll
        for (int p = 0; p < 28; p++) {
            const int i = PI_[p], j = PJ_[p];
            const float phi = scpl[i * 8 + j];
            const int b = ((tid >> (7 - i)) ^ (tid >> (7 - j))) & 1;
            th += b ? -0.5f * phi : 0.5f * phi;
        }
        float s, c;
        __sincosf(th, &s, &c);
        sD[tid] = make_float2(c, -s);
    }

    if (wid == 0) {
        float mn = fminf(scpl[lane], scpl[lane + 32]);
        float mx = fmaxf(scpl[lane], scpl[lane + 32]);
#pragma unroll
        for (int o = 16; o; o >>= 1) {
            mn = fminf(mn, __shfl_xor_sync(0xffffffffu, mn, o));
            mx = fmaxf(mx, __shfl_xor_sync(0xffffffffu, mx, o));
        }
        const float range = mx - mn;
        bool bit = false;
        if (lane < 28)
            bit = (scpl[PI_[lane] * 8 + PJ_[lane]] - mn) / range > 0.5f;
        const unsigned am = __ballot_sync(0xffffffffu, bit);
        if (lane == 0) amask_sh = am;
    } else if (tid >= 128 && tid < 136) {
        // u' = H * Rz*Ry*Rx for qubit q
        const int q = tid - 128;
        float sx, cx, sy, cy, sz, cz;
        __sincosf(0.5f * sw[q],      &sx, &cx);
        __sincosf(0.5f * sw[q + 8],  &sy, &cy);
        __sincosf(0.5f * sw[q + 16], &sz, &cz);
        const float2 A00 = make_float2(cy * cx,  sy * sx);
        const float2 A01 = make_float2(-sy * cx, -cy * sx);
        const float2 A10 = make_float2( sy * cx, -cy * sx);
        const float2 A11 = make_float2(cy * cx, -sy * sx);
        const float2 ez  = make_float2(cz, -sz);
        const float2 ezc = make_float2(cz,  sz);
        const float2 u00 = cmul(ez,  A00);
        const float2 u01 = cmul(ez,  A01);
        const float2 u10 = cmul(ezc, A10);
        const float2 u11 = cmul(ezc, A11);
        u1s[q][0] = make_float2(SQ2 * (u00.x + u10.x), SQ2 * (u00.y + u10.y));
        u1s[q][1] = make_float2(SQ2 * (u01.x + u11.x), SQ2 * (u01.y + u11.y));
        u1s[q][2] = make_float2(SQ2 * (u00.x - u10.x), SQ2 * (u00.y - u10.y));
        u1s[q][3] = make_float2(SQ2 * (u01.x - u11.x), SQ2 * (u01.y - u11.y));
    }
    __syncthreads();                               // sync1
    const unsigned amask = amask_sh;

    // ---------------- phase 2 ----------------
    if (tid < 112) {
        const int p   = tid >> 2;
        const int col = tid & 3;
        const int widx = 3 * NQ + 6 * __popc(amask & ((1u << p) - 1u));

        float2 v0 = make_float2(col == 0 ? 1.f : 0.f, 0.f);
        float2 v1 = make_float2(col == 1 ? 1.f : 0.f, 0.f);
        float2 v2 = make_float2(col == 2 ? 1.f : 0.f, 0.f);
        float2 v3 = make_float2(col == 3 ? 1.f : 0.f, 0.f);

#define PHASE_I(er, ei) { const float2 e = make_float2(er, ei), ec = make_float2(er, -(ei)); \
        v0 = cmul(v0, e); v1 = cmul(v1, e); v2 = cmul(v2, ec); v3 = cmul(v3, ec); }
#define PHASE_J(er, ei) { const float2 e = make_float2(er, ei), ec = make_float2(er, -(ei)); \
        v0 = cmul(v0, e); v1 = cmul(v1, ec); v2 = cmul(v2, e); v3 = cmul(v3, ec); }
#define RY_J(c, s) { float2 t; \
        t  = make_float2((c)*v0.x - (s)*v1.x, (c)*v0.y - (s)*v1.y); \
        v1 = make_float2((s)*v0.x + (c)*v1.x, (s)*v0.y + (c)*v1.y); v0 = t; \
        t  = make_float2((c)*v2.x - (s)*v3.x, (c)*v2.y - (s)*v3.y); \
        v3 = make_float2((s)*v2.x + (c)*v3.x, (s)*v2.y + (c)*v3.y); v2 = t; }
#define SWAP13 { const float2 t = v1; v1 = v3; v3 = t; }
#define SWAP23 { const float2 t = v2; v2 = v3; v3 = t; }

        float s0, c0, s1, c1, s2, c2, s3, c3, s4, c4, s5, c5;
        __sincosf(0.5f * sw[widx + 0], &s0, &c0);
        __sincosf(0.5f * sw[widx + 1], &s1, &c1);
        __sincosf(0.5f * sw[widx + 2], &s2, &c2);
        __sincosf(0.5f * sw[widx + 3], &s3, &c3);
        __sincosf(0.5f * sw[widx + 4], &s4, &c4);
        __sincosf(0.5f * sw[widx + 5], &s5, &c5);

        PHASE_J(SQ2,  SQ2);
        SWAP13;
        PHASE_I(c0, -s0);
        RY_J(c1, s1);
        SWAP23;
        RY_J(c2, s2);
        SWAP13;
        PHASE_I(SQ2, -SQ2);
        PHASE_J(SQ2,  SQ2);
        SWAP13;
        PHASE_I(c3, -s3);
        RY_J(c4, s4);
        SWAP23;
        RY_J(c5, s5);

        pairM[p][0 * 4 + col] = v0;
        pairM[p][1 * 4 + col] = v1;
        pairM[p][2 * 4 + col] = v2;
        pairM[p][3 * 4 + col] = v3;
#undef PHASE_I
#undef PHASE_J
#undef RY_J
#undef SWAP13
#undef SWAP23
    } else if (tid < 176) {
        const int t   = tid - 112;
        const int g   = t >> 4;
        const int row = (t >> 2) & 3;
        const int col = t & 3;
        const float2 ea = u1s[2 * g][(row >> 1) * 2 + (col >> 1)];
        const float2 eb = u1s[2 * g + 1][(row & 1) * 2 + (col & 1)];
        u2s[g][row * 4 + col] = cmul(ea, eb);
    } else if (tid == 192) {
        int n = 0;
#pragma unroll
        for (int p = 0; p < 28; p++) {
            if ((amask >> p) & 1u) {
                const int mi = 1 << (7 - PI_[p]);
                const int mj = 1 << (7 - PJ_[p]);
                int e = p | (mi << 8) | (mj << 16);
                if ((mi | mj) < 32) e |= 1 << 24;   // intra-warp step
                actL[n++] = e;
            }
        }
        actN_sh = n;
    }
    __syncthreads();                               // sync2: chain start
    const int actN = actN_sh;

    int cp = 0;

    // ---- 4 paired single-qubit 4x4 steps (H folded; D folded into last) ----
    // leading-sync scheme: sync type chosen by THIS step's read mask.
#pragma unroll
    for (int g = 0; g < 4; g++) {
        if (g == 1) __syncthreads();               // step reads bits (5,4)
        else if (g >= 2) __syncwarp(0xffffffffu);  // bits (3,2) / (1,0): intra
        // g == 0: sync2 covers
        const int ba = 7 - 2 * g, bb = 6 - 2 * g;
        const int ma = 1 << ba, mb = 1 << bb;
        const int row  = (((tid >> ba) & 1) << 1) | ((tid >> bb) & 1);
        const int base = tid & ~(ma | mb);
        const float2* M = &u2s[g][row * 4];
        float2 r = cmul(M[0], buf[cp][base]);
        r = cmad(r, M[1], buf[cp][base | mb]);
        r = cmad(r, M[2], buf[cp][base | ma]);
        r = cmad(r, M[3], buf[cp][base | ma | mb]);
        if (g == 3) r = cmul(sD[tid], r);
        buf[cp ^ 1][tid] = r;
        cp ^= 1;
    }

    // ---- 4 H(x)H steps ----
#pragma unroll
    for (int g = 0; g < 4; g++) {
        if (g < 2) __syncthreads();                // bits (7,6) / (5,4)
        else       __syncwarp(0xffffffffu);        // bits (3,2) / (1,0)
        const int ba = 7 - 2 * g, bb = 6 - 2 * g;
        const int ma = 1 << ba, mb = 1 << bb;
        const int base = tid & ~(ma | mb);
        const float sa = (tid & ma) ? -1.f : 1.f;
        const float sb = (tid & mb) ? -1.f : 1.f;
        const float2 a00 = buf[cp][base];
        const float2 a01 = buf[cp][base | mb];
        const float2 a10 = buf[cp][base | ma];
        const float2 a11 = buf[cp][base | ma | mb];
        float2 r;
        r.x = 0.5f * ((a00.x + sb * a01.x) + sa * (a10.x + sb * a11.x));
        r.y = 0.5f * ((a00.y + sb * a01.y) + sa * (a10.y + sb * a11.y));
        buf[cp ^ 1][tid] = r;
        cp ^= 1;
    }

    // ---- dense conv+pool 4x4 applies ----
#pragma unroll 1
    for (int a = 0; a < actN; a++) {
        const int packed = actL[a];
        if (packed & (1 << 24)) __syncwarp(0xffffffffu);
        else                    __syncthreads();
        const int p  = packed & 255;
        const int mi = (packed >> 8) & 255;
        const int mj = (packed >> 16) & 255;
        const int row  = ((tid & mi) ? 2 : 0) | ((tid & mj) ? 1 : 0);
        const int base = tid & ~(mi | mj);
        const float2* M = &pairM[p][row * 4];
        float2 r = cmul(M[0], buf[cp][base]);
        r = cmad(r, M[1], buf[cp][base | mj]);
        r = cmad(r, M[2], buf[cp][base | mi]);
        r = cmad(r, M[3], buf[cp][base | mi | mj]);
        buf[cp ^ 1][tid] = r;
        cp ^= 1;
    }

    __syncthreads();                               // epilogue reads cross-warp

    if (mode == 1) {
        g_psi[tid] = buf[cp][tid];
        return;
    }

    // ---- write this block's 4-row output slice (real part) ----
    const float2* ps = buf[cp];
    const int r = (blockIdx.x << 2) | (tid >> 6);
    const int q = tid & 63;
    const float2 a  = ps[r];
    const float2 b0 = ps[(q << 2)];
    const float2 b1 = ps[(q << 2) + 1];
    const float2 b2 = ps[(q << 2) + 2];
    const float2 b3 = ps[(q << 2) + 3];
    float4 o;
    o.x = a.x * b0.x + a.y * b0.y;
    o.y = a.x * b1.x + a.y * b1.y;
    o.z = a.x * b2.x + a.y * b2.y;
    o.w = a.x * b3.x + a.y * b3.y;
    out[(r << 6) + q] = o;
}

// fallback for unexpected out_size (planar [Re|Im])
__global__ void __launch_bounds__(256)
outer_planar_kernel(float* __restrict__ out) {
    const int r = blockIdx.x;
    const int c = threadIdx.x;
    const float2 a = g_psi[r];
    const float2 b = g_psi[c];
    out[r * DIM + c]             = a.x * b.x + a.y * b.y;
    out[DIM * DIM + r * DIM + c] = a.y * b.x - a.x * b.y;
}

extern "C" void kernel_launch(void* const* d_in, const int* in_sizes, int n_in,
                              void* d_out, int out_size) {
    const float* x   = nullptr;
    const float* w   = nullptr;
    const float* cpl = nullptr;
    for (int i = 0; i < n_in; i++) {
        if      (in_sizes[i] == 256) x   = (const float*)d_in[i];
        else if (in_sizes[i] == 210) w   = (const float*)d_in[i];
        else if (in_sizes[i] == 64)  cpl = (const float*)d_in[i];
    }

    if (out_size == DIM * DIM) {
        fused_kernel<<<64, 256>>>(x, w, cpl, (float4*)d_out, 0);
    } else {
        fused_kernel<<<1, 256>>>(x, w, cpl, (float4*)d_out, 1);
        outer_planar_kernel<<<DIM, DIM>>>((float*)d_out);
    }
}